// round 11
// baseline (speedup 1.0000x reference)
#include <cuda_runtime.h>

#define IMG_H 1024
#define IMG_W 1024
#define NBATCH 16
#define NPIX (NBATCH * IMG_H * IMG_W)
#define OVF_CAP (1u << 23)
#define FULLM 0xffffffffu
#define M34 ((1ull << 34) - 1ull)

// k_front tiling: 64x64 output, +/-4 halo
#define TS 64
#define TIN 72      // input tile  (TS+8)
#define THB 68      // h-blurred / S / mag stride (TS+4)

// ---------------- scratch (static device globals; no allocation) ----------------
__device__ float    g_tu[NPIX];          // SQUARED NMS-surviving magnitude
__device__ unsigned g_bmax[NBATCH];      // per-batch max mag^2 (float bits)
__device__ unsigned g_tumax[NBATCH];     // per-batch max thin^2 (float bits)
__device__ float    g_lo2[NBATCH];
__device__ float    g_hi2[NBATCH];
__device__ unsigned g_ovfn[2];
__device__ unsigned g_ovfq[2][OVF_CAP];
__device__ unsigned g_bar_cnt;
__device__ unsigned g_bar_gen;

__constant__ int c_dy[8] = {0, 1, 1, 1, 0, -1, -1, -1};
__constant__ int c_dx[8] = {1, 1, 0, -1, -1, -1, 0, 1};

#define GW0 0.13533528323661270f
#define GW1 0.60653065971263342f
#define T1C 0.41421356237309503f
#define T2C 2.41421356237309510f
#define LOW_T_C 0.00392f
#define HIGH_T_C 0.15f
#define STRONG_BITS 0x437F0000u

// ---------------- K0 ----------------
__global__ void k_init() {
    int t = threadIdx.x;
    if (t < NBATCH) { g_bmax[t] = 0u; g_tumax[t] = 0u; }
    if (t < 2) g_ovfn[t] = 0u;
    if (t == 0) { g_bar_cnt = 0u; g_bar_gen = 0u; }
}

__device__ __forceinline__ int sector_of(float Ix, float Iy) {
    float axv = fabsf(Ix), ayv = fabsf(Iy);
    if (ayv <= T1C * axv)       return (Ix >= 0.f) ? 4 : 0;
    else if (ayv >= T2C * axv)  return (Iy > 0.f) ? 6 : 2;
    else                        return (Iy > 0.f) ? ((Ix > 0.f) ? 5 : 7)
                                                  : ((Ix > 0.f) ? 3 : 1);
}

// ---------------- K1 bodies -------------------------------------------------------
// Shared tail: NMS + reduction (mag in sB with stride THB, sectors in sK)
__device__ __forceinline__ void front_tail(float* sB, unsigned char* sK,
                                           float* red1, float* red2, float bm0) {
    const int bb  = blockIdx.z;
    const int gy0 = blockIdx.y * TS, gx0 = blockIdx.x * TS;
    const int tid = threadIdx.x;
    const int tx = tid & 63, tyq = tid >> 6;
    float bm = bm0, tm = 0.f;
#pragma unroll
    for (int j = 0; j < 4; j++) {
        int oy = tyq + j * 16, ox = tx;
        float mc = sB[(oy + 1) * THB + (ox + 1)];
        int k = sK[oy * TS + ox];
        int dy = c_dy[k], dx = c_dx[k];
        float mp = sB[(oy + 1 + dy) * THB + (ox + 1 + dx)];
        float mn = sB[(oy + 1 - dy) * THB + (ox + 1 - dx)];
        float tu = (mc > mp && mc > mn) ? mc : 0.f;
        unsigned p = ((unsigned)bb << 20) | ((unsigned)(gy0 + oy) << 10) | (unsigned)(gx0 + ox);
        g_tu[p] = tu;
        bm = fmaxf(bm, mc); tm = fmaxf(tm, tu);
    }
    for (int o = 16; o; o >>= 1) {
        bm = fmaxf(bm, __shfl_xor_sync(FULLM, bm, o));
        tm = fmaxf(tm, __shfl_xor_sync(FULLM, tm, o));
    }
    if ((tid & 31) == 0) { red1[tid >> 5] = bm; red2[tid >> 5] = tm; }
    __syncthreads();
    if (tid < 32) {
        bm = red1[tid]; tm = red2[tid];
        for (int o = 16; o; o >>= 1) {
            bm = fmaxf(bm, __shfl_xor_sync(FULLM, bm, o));
            tm = fmaxf(tm, __shfl_xor_sync(FULLM, tm, o));
        }
        if (tid == 0) {
            atomicMax(&g_bmax[bb],  __float_as_uint(bm));
            atomicMax(&g_tumax[bb], __float_as_uint(tm));
        }
    }
}

// Border path: scalar with bounds checks (60 of 256 blocks per batch)
__device__ __forceinline__ void front_border(const float* __restrict__ img,
                                             float* sA, float* sB, unsigned char* sK,
                                             float* red1, float* red2) {
    const int bb  = blockIdx.z;
    const int gy0 = blockIdx.y * TS, gx0 = blockIdx.x * TS;
    const int tid = threadIdx.x;
    const float* im = img + bb * (IMG_H * IMG_W);

    for (int i = tid; i < TIN * TIN; i += 1024) {
        int ay = i / TIN, ax = i - ay * TIN;
        int gy = gy0 - 4 + ay, gx = gx0 - 4 + ax;
        float v = 0.f;
        if ((unsigned)gy < IMG_H && (unsigned)gx < IMG_W) v = __ldg(&im[gy * IMG_W + gx]);
        sA[i] = v;
    }
    __syncthreads();

    for (int i = tid; i < TIN * THB; i += 1024) {
        int hy = i / THB, hx = i - hy * THB;
        const float* r = &sA[hy * TIN + hx];
        sB[i] = GW0 * r[0] + GW1 * r[1] + r[2] + GW1 * r[3] + GW0 * r[4];
    }
    __syncthreads();

    for (int i = tid; i < THB * THB; i += 1024) {
        int sy = i / THB, sx = i - sy * THB;
        const float* r = &sB[sy * THB + sx];
        float v = GW0 * r[0] + GW1 * r[THB] + r[2 * THB] + GW1 * r[3 * THB] + GW0 * r[4 * THB];
        int gy = gy0 - 2 + sy, gx = gx0 - 2 + sx;
        if ((unsigned)gy >= IMG_H || (unsigned)gx >= IMG_W) v = 0.f;
        sA[sy * THB + sx] = v;
    }
    __syncthreads();

    for (int i = tid; i < 66 * 66; i += 1024) {
        int my = i / 66, mx = i - my * 66;
        const float* s = &sA[my * THB + mx];
        float s00 = s[0],       s01 = s[1],           s02 = s[2];
        float s10 = s[THB],                           s12 = s[THB + 2];
        float s20 = s[2 * THB], s21 = s[2 * THB + 1], s22 = s[2 * THB + 2];
        float Ix = (s00 - s02) + 2.f * (s10 - s12) + (s20 - s22);
        float Iy = (s00 + 2.f * s01 + s02) - (s20 + 2.f * s21 + s22);
        float m = Ix * Ix + Iy * Iy;
        int gy = gy0 - 1 + my, gx = gx0 - 1 + mx;
        if ((unsigned)gy >= IMG_H || (unsigned)gx >= IMG_W) { m = 0.f; Ix = 0.f; Iy = 0.f; }
        sB[my * THB + mx] = m;
        if ((unsigned)(my - 1) < TS && (unsigned)(mx - 1) < TS)
            sK[(my - 1) * TS + (mx - 1)] = (unsigned char)sector_of(Ix, Iy);
    }
    __syncthreads();
    front_tail(sB, sK, red1, red2, 0.f);
}

// Interior path: float4-vectorized, no bounds checks (196 of 256 blocks per batch)
__device__ __forceinline__ void front_interior(const float* __restrict__ img,
                                               float* sA, float* sB, unsigned char* sK,
                                               float* red1, float* red2) {
    const int bb  = blockIdx.z;
    const int gy0 = blockIdx.y * TS, gx0 = blockIdx.x * TS;
    const int tid = threadIdx.x;
    const float* org = img + bb * (IMG_H * IMG_W) + (gy0 - 4) * IMG_W + (gx0 - 4);

    // load 72x72 as 72 x 18 float4 (global and smem rows both 16B-aligned)
#pragma unroll
    for (int j = 0; j < 2; j++) {
        int i = tid + j * 1024;
        if (i < 1296) {
            int ay = i / 18, ax4 = i - ay * 18;
            float4 v = __ldg((const float4*)(org + ay * IMG_W) + ax4);
            *((float4*)(sA + ay * TIN) + ax4) = v;
        }
    }
    __syncthreads();

    // horizontal blur: 72 rows x 17 float4 -> sB (stride THB)
#pragma unroll
    for (int j = 0; j < 2; j++) {
        int i = tid + j * 1024;
        if (i < 1224) {
            int hy = i / 17, hx4 = i - hy * 17;
            const float* r = sA + hy * TIN + hx4 * 4;
            float4 a = *(const float4*)r;
            float4 b = *(const float4*)(r + 4);
            float4 o;
            o.x = GW0 * a.x + GW1 * a.y + a.z + GW1 * a.w + GW0 * b.x;
            o.y = GW0 * a.y + GW1 * a.z + a.w + GW1 * b.x + GW0 * b.y;
            o.z = GW0 * a.z + GW1 * a.w + b.x + GW1 * b.y + GW0 * b.z;
            o.w = GW0 * a.w + GW1 * b.x + b.y + GW1 * b.z + GW0 * b.w;
            *((float4*)(sB + hy * THB) + hx4) = o;
        }
    }
    __syncthreads();

    // vertical blur: 68 rows x 17 float4 -> sA (stride THB)
#pragma unroll
    for (int j = 0; j < 2; j++) {
        int i = tid + j * 1024;
        if (i < 1156) {
            int sy = i / 17, sx4 = i - sy * 17;
            const float4* r = (const float4*)(sB + sy * THB) + sx4;
            float4 r0 = r[0], r1 = r[17], r2 = r[34], r3 = r[51], r4 = r[68];
            float4 o;
            o.x = GW0 * r0.x + GW1 * r1.x + r2.x + GW1 * r3.x + GW0 * r4.x;
            o.y = GW0 * r0.y + GW1 * r1.y + r2.y + GW1 * r3.y + GW0 * r4.y;
            o.z = GW0 * r0.z + GW1 * r1.z + r2.z + GW1 * r3.z + GW0 * r4.z;
            o.w = GW0 * r0.w + GW1 * r1.w + r2.w + GW1 * r3.w + GW0 * r4.w;
            *((float4*)(sA + sy * THB) + sx4) = o;
        }
    }
    __syncthreads();

    // mag^2 + sector: 66 rows x 17 float4 -> sB (stride THB; last 2 cols garbage, unread)
#pragma unroll
    for (int j = 0; j < 2; j++) {
        int i = tid + j * 1024;
        if (i < 1122) {
            int my = i / 17, mx4 = i - my * 17;
            int mx = mx4 * 4;
            const float* r0 = sA + my * THB + mx;
            const float* r1 = r0 + THB;
            const float* r2 = r1 + THB;
            float4 a0 = *(const float4*)r0; float e0 = r0[4], f0 = r0[5];
            float4 a1 = *(const float4*)r1; float e1 = r1[4], f1 = r1[5];
            float4 a2 = *(const float4*)r2; float e2 = r2[4], f2 = r2[5];
            float4 mg;
            float ix0 = (a0.x - a0.z) + 2.f * (a1.x - a1.z) + (a2.x - a2.z);
            float iy0 = (a0.x + 2.f * a0.y + a0.z) - (a2.x + 2.f * a2.y + a2.z);
            float ix1 = (a0.y - a0.w) + 2.f * (a1.y - a1.w) + (a2.y - a2.w);
            float iy1 = (a0.y + 2.f * a0.z + a0.w) - (a2.y + 2.f * a2.z + a2.w);
            float ix2 = (a0.z - e0) + 2.f * (a1.z - e1) + (a2.z - e2);
            float iy2 = (a0.z + 2.f * a0.w + e0) - (a2.z + 2.f * a2.w + e2);
            float ix3 = (a0.w - f0) + 2.f * (a1.w - f1) + (a2.w - f2);
            float iy3 = (a0.w + 2.f * e0 + f0) - (a2.w + 2.f * e2 + f2);
            mg.x = ix0 * ix0 + iy0 * iy0;
            mg.y = ix1 * ix1 + iy1 * iy1;
            mg.z = ix2 * ix2 + iy2 * iy2;
            mg.w = ix3 * ix3 + iy3 * iy3;
            *((float4*)(sB + my * THB) + mx4) = mg;
            if ((unsigned)(my - 1) < TS) {
                unsigned char* kr = sK + (my - 1) * TS - 1;   // col c -> kr[c]
                if ((unsigned)(mx + 0 - 1) < TS) kr[mx + 0] = (unsigned char)sector_of(ix0, iy0);
                if ((unsigned)(mx + 1 - 1) < TS) kr[mx + 1] = (unsigned char)sector_of(ix1, iy1);
                if ((unsigned)(mx + 2 - 1) < TS) kr[mx + 2] = (unsigned char)sector_of(ix2, iy2);
                if ((unsigned)(mx + 3 - 1) < TS) kr[mx + 3] = (unsigned char)sector_of(ix3, iy3);
            }
        }
    }
    __syncthreads();
    front_tail(sB, sK, red1, red2, 0.f);
}

__global__ __launch_bounds__(1024) void k_front(const float* __restrict__ img) {
    __shared__ float sA[TIN * TIN];
    __shared__ float sB[TIN * THB];
    __shared__ unsigned char sK[TS * TS];
    __shared__ float red1[32], red2[32];
    bool border = (blockIdx.x == 0) | (blockIdx.x == gridDim.x - 1) |
                  (blockIdx.y == 0) | (blockIdx.y == gridDim.y - 1);
    if (border) front_border(img, sA, sB, sK, red1, red2);
    else        front_interior(img, sA, sB, sK, red1, red2);
}

// ---------------- K1.5: per-batch squared thresholds ------------------------------
__global__ void k_thresh() {
    __shared__ float s_hi;
    int t = threadIdx.x;
    if (t == 0) {
        float tmax = 0.f;
#pragma unroll
        for (int i = 0; i < NBATCH; i++) {
            float bm2 = __uint_as_float(g_bmax[i]);
            float tm2 = __uint_as_float(g_tumax[i]);
            if (bm2 > 0.f) tmax = fmaxf(tmax, sqrtf(tm2) / sqrtf(bm2));
        }
        s_hi = tmax * HIGH_T_C;
    }
    __syncthreads();
    if (t < NBATCH) {
        float bm = sqrtf(__uint_as_float(g_bmax[t]));
        float lo = LOW_T_C * bm, hi = s_hi * bm;
        g_lo2[t] = lo * lo;
        g_hi2[t] = hi * hi;
    }
}

// ---------------- bounded DFS expansion (claim via CAS) ---------------------------
__device__ __forceinline__ void expand_from(unsigned seed, float* out,
                                            float lo2, float hi2,
                                            int qidx, int maxpops) {
    unsigned stk[96];
    int sp = 0, pops = 0;
    unsigned cur = seed;
    const unsigned base = cur & ~0xFFFFFu;
    while (true) {
        int y = (cur >> 10) & 1023;
        int x = cur & 1023;
#pragma unroll
        for (int d = 0; d < 8; d++) {
            int ny = y + c_dy[d], nx = x + c_dx[d];
            if ((unsigned)ny < IMG_H && (unsigned)nx < IMG_W) {
                unsigned n = base | ((unsigned)ny << 10) | (unsigned)nx;
                float t = __ldg(&g_tu[n]);
                if (t < hi2 && t >= lo2) {
                    unsigned old = atomicCAS((unsigned*)&out[n], 0u, STRONG_BITS);
                    if (old == 0u) {
                        if (sp < 96) stk[sp++] = n;
                        else {
                            unsigned pos = atomicAdd(&g_ovfn[qidx], 1u);
                            if (pos < OVF_CAP) g_ovfq[qidx][pos] = n;
                        }
                    }
                }
            }
        }
        if (sp == 0) break;
        if (++pops > maxpops) {
            while (sp > 0) {
                unsigned v = stk[--sp];
                unsigned pos = atomicAdd(&g_ovfn[qidx], 1u);
                if (pos < OVF_CAP) g_ovfq[qidx][pos] = v;
            }
            break;
        }
        cur = stk[--sp];
    }
}

// ---------------- K2: warp-bitboard tile hysteresis + inline cross-tile expansion --
__global__ __launch_bounds__(256) void k_seed(float* __restrict__ out) {
    const int lane = threadIdx.x & 31;
    const int tileId = blockIdx.x * 8 + (threadIdx.x >> 5);   // 16384 32x32 tiles
    const int bb = tileId >> 10;
    const int t  = tileId & 1023;
    const int gy0 = (t >> 5) << 5, gx0 = (t & 31) << 5;
    const float* tu = g_tu + (bb << 20);
    const float hi2 = g_hi2[bb], lo2 = g_lo2[bb];

    unsigned long long sm = 0, wm = 0;
    unsigned long long ht_s = 0, ht_w = 0;
    unsigned long long hb_s = 0, hb_w = 0;

    for (int r = 0; r < 34; r++) {
        int gy = gy0 - 1 + r;
        float v = 0.f, v2 = 0.f;
        if ((unsigned)gy < IMG_H) {
            int gx = gx0 - 1 + lane;
            if ((unsigned)gx < IMG_W) v = __ldg(&tu[(gy << 10) + gx]);
            int gx2 = gx0 + 31 + lane;
            if (lane < 2 && (unsigned)gx2 < IMG_W) v2 = __ldg(&tu[(gy << 10) + gx2]);
        }
        unsigned bs  = __ballot_sync(FULLM, v >= hi2);
        unsigned bw  = __ballot_sync(FULLM, v >= lo2 && v < hi2);
        unsigned bs2 = __ballot_sync(FULLM, lane < 2 && v2 >= hi2);
        unsigned bw2 = __ballot_sync(FULLM, lane < 2 && v2 >= lo2 && v2 < hi2);
        unsigned long long rs = (unsigned long long)bs | ((unsigned long long)(bs2 & 3u) << 32);
        unsigned long long rw = (unsigned long long)bw | ((unsigned long long)(bw2 & 3u) << 32);
        if (r == 0)        { ht_s = rs; ht_w = rw; }
        else if (r == 33)  { hb_s = rs; hb_w = rw; }
        else if (lane == r - 1) { sm = rs; wm = rw; }
    }

    // fixpoint: s |= w & dilate8(s)
    unsigned long long s = sm, hts = ht_s, hbs = hb_s;
    while (true) {
        unsigned long long up = __shfl_up_sync(FULLM, s, 1);
        if (lane == 0)  up = hts;
        unsigned long long dn = __shfl_down_sync(FULLM, s, 1);
        if (lane == 31) dn = hbs;
        unsigned long long dil = (s << 1) | (s >> 1)
                               | up | (up << 1) | (up >> 1)
                               | dn | (dn << 1) | (dn >> 1);
        unsigned long long ns = s | (wm & dil & M34);
        unsigned long long row0  = __shfl_sync(FULLM, s, 0);
        unsigned long long row31 = __shfl_sync(FULLM, s, 31);
        unsigned long long nht = hts | (ht_w & ((hts << 1) | (hts >> 1) | row0  | (row0 << 1)  | (row0 >> 1))  & M34);
        unsigned long long nhb = hbs | (hb_w & ((hbs << 1) | (hbs >> 1) | row31 | (row31 << 1) | (row31 >> 1)) & M34);
        bool ch = (ns != s) || (nht != hts) || (nhb != hbs);
        s = ns; hts = nht; hbs = nhb;
        if (!__any_sync(FULLM, ch)) break;
    }

    // sparse coalesced 255 writes (out pre-zeroed by memset)
    const unsigned obase = ((unsigned)bb << 20) + ((unsigned)gy0 << 10) + (unsigned)gx0;
#pragma unroll 4
    for (int r = 0; r < 32; r++) {
        unsigned long long m = __shfl_sync(FULLM, s, r);
        if ((m >> (lane + 1)) & 1ull)
            out[obase + ((unsigned)r << 10) + lane] = 255.0f;
    }

    // inline expansion from promoted interior pixels with out-of-tile weak neighbor
    unsigned long long prom = s & ~sm;
    unsigned long long wup = __shfl_up_sync(FULLM, wm, 1);
    if (lane == 0)  wup = ht_w;
    unsigned long long wdn = __shfl_down_sync(FULLM, wm, 1);
    if (lane == 31) wdn = hb_w;
    unsigned long long wvert = wup | wm | wdn;
    unsigned long long oow = 0;
    if (wvert & 1ull)            oow |= 2ull;
    if ((wvert >> 33) & 1ull)    oow |= (1ull << 32);
    if (lane == 0)  oow |= (ht_w | (ht_w << 1) | (ht_w >> 1));
    if (lane == 31) oow |= (hb_w | (hb_w << 1) | (hb_w >> 1));
    unsigned long long push = prom & oow & 0x1FFFFFFFEull;
    while (push) {
        int c = __ffsll((long long)push) - 1;
        push &= push - 1;
        unsigned p = ((unsigned)bb << 20) | ((unsigned)(gy0 + lane) << 10) | (unsigned)(gx0 + c - 1);
        expand_from(p, out, lo2, hi2, 0, 96);
    }
}

// ---------------- K3: persistent drain (backstop for spills) ----------------------
__device__ __forceinline__ void gsync() {
    __syncthreads();
    if (threadIdx.x == 0) {
        unsigned gen = atomicAdd(&g_bar_gen, 0u);
        __threadfence();
        if (atomicAdd(&g_bar_cnt, 1u) == gridDim.x - 1) {
            atomicExch(&g_bar_cnt, 0u);
            __threadfence();
            atomicAdd(&g_bar_gen, 1u);
        } else {
            while (atomicAdd(&g_bar_gen, 0u) == gen) __nanosleep(100);
        }
        __threadfence();
    }
    __syncthreads();
}

__global__ __launch_bounds__(256, 2) void k_drain(float* __restrict__ out) {
    int curq = 0;
    while (true) {
        unsigned n = atomicAdd(&g_ovfn[curq], 0u);
        if (n == 0u) break;
        if (n > OVF_CAP) n = OVF_CAP;
        const unsigned stride = gridDim.x * blockDim.x;
        for (unsigned i = blockIdx.x * blockDim.x + threadIdx.x; i < n; i += stride) {
            unsigned p = __ldcg(&g_ovfq[curq][i]);
            int bb = p >> 20;
            expand_from(p, out, g_lo2[bb], g_hi2[bb], curq ^ 1, 64);
        }
        gsync();
        if (blockIdx.x == 0 && threadIdx.x == 0) atomicExch(&g_ovfn[curq], 0u);
        gsync();
        curq ^= 1;
    }
}

// ---------------- launch ----------------
extern "C" void kernel_launch(void* const* d_in, const int* in_sizes, int n_in,
                              void* d_out, int out_size) {
    const float* img = (const float*)d_in[0];
    float* out = (float*)d_out;
    (void)in_sizes; (void)n_in; (void)out_size;

    k_init<<<1, 32>>>();
    cudaMemsetAsync(out, 0, (size_t)NPIX * sizeof(float));
    dim3 b1(1024), g1(IMG_W / TS, IMG_H / TS, NBATCH);
    k_front<<<g1, b1>>>(img);
    k_thresh<<<1, 32>>>();
    k_seed<<<2048, 256>>>(out);
    k_drain<<<296, 256>>>(out);
}